// round 10
// baseline (speedup 1.0000x reference)
#include <cuda_runtime.h>
#include <cuda_fp16.h>
#include <cstdint>

#define NPIX 9216
#define LAB  21
#define HH   96
#define WW   96
#define RAD  9
#define KWD  (2*RAD+1)
#define NBLK 72                 // 9216 / 128

// ---- scratch (device globals: allocation-free kernel_launch) ----
__device__ __half g_Kh[(size_t)NPIX * NPIX];   // only upper-tri 128-tiles written (~85MB touched)
__device__ float g_feats[NPIX * 5];
__device__ float g_rowsum[NPIX];
__device__ float g_nbi[NPIX];
__device__ float g_nsp[NPIX];
__device__ float g_kw[KWD];
__device__ float g_Q[LAB * NPIX];              // [L][N]
__device__ float g_tmp[LAB * NPIX];            // y-conv intermediate
__device__ __half g_VT[32 * NPIX];             // (nbi*Q)^T, rows 21..31 zero
__device__ float g_Cp[4 * NPIX * LAB];         // k-split partials of K @ V, [s][N][L]

// ===========================================================================
// helpers
// ===========================================================================
__device__ __forceinline__ uint32_t smem_u32(const void* p) {
    uint32_t a;
    asm("{ .reg .u64 t; cvta.to.shared.u64 t, %1; cvt.u32.u64 %0, t; }" : "=r"(a) : "l"(p));
    return a;
}
__device__ __forceinline__ uint32_t swz(uint32_t off) {   // 8x128B xor swizzle
    return off ^ ((off >> 3) & 0x70);
}
__device__ __forceinline__ void cp16(uint32_t dst, const void* src) {
    asm volatile("cp.async.cg.shared.global [%0], [%1], 16;" :: "r"(dst), "l"(src) : "memory");
}

// ===========================================================================
// Prep
// ===========================================================================
__global__ void k_prep(const float* __restrict__ I) {
    int n = blockIdx.x * blockDim.x + threadIdx.x;
    if (n >= NPIX) return;
    int y = n / WW, x = n % WW;

    if (n < KWD) {
        float d = (float)(n - RAD) / 3.0f;
        g_kw[n] = expf(-0.5f * d * d);
    }
    float sy = 0.f, sx = 0.f;
    #pragma unroll
    for (int d = -RAD; d <= RAD; d++) {
        float t = (float)d / 3.0f;
        float w = expf(-0.5f * t * t);
        if ((unsigned)(y + d) < HH) sy += w;
        if ((unsigned)(x + d) < WW) sx += w;
    }
    g_nsp[n] = rsqrtf(sy * sx);
    g_rowsum[n] = 0.f;

    g_feats[n * 5 + 0] = (float)x / 80.0f;
    g_feats[n * 5 + 1] = (float)y / 80.0f;
    g_feats[n * 5 + 2] = I[0 * NPIX + n] / 13.0f;
    g_feats[n * 5 + 3] = I[1 * NPIX + n] / 13.0f;
    g_feats[n * 5 + 4] = I[2 * NPIX + n] / 13.0f;

    __half z = __float2half(0.f);
    #pragma unroll
    for (int l = LAB; l < 32; l++) g_VT[l * NPIX + n] = z;
}

// ===========================================================================
// Build K (fp16), upper-triangle 128x128 tiles only. Row sums via atomics.
// ===========================================================================
#define TSTR 136
__global__ void __launch_bounds__(256) k_buildK() {
    __shared__ float fA[128 * 5];
    __shared__ float fB[128 * 5];
    __shared__ __align__(16) unsigned short tile[128 * TSTR];

    int id = blockIdx.x;
    int bi;
    {
        float b = 2.f * NBLK + 1.f;
        bi = (int)((b - sqrtf(b * b - 8.f * (float)id)) * 0.5f);
        if (bi < 0) bi = 0;
        if (bi > NBLK - 1) bi = NBLK - 1;
        while (bi * NBLK - bi * (bi - 1) / 2 > id) bi--;
        while ((bi + 1) * NBLK - (bi + 1) * bi / 2 <= id) bi++;
    }
    int bj = bi + (id - (bi * NBLK - bi * (bi - 1) / 2));

    int tid = threadIdx.x;
    for (int i = tid; i < 640; i += 256) {
        fA[i] = g_feats[bi * 640 + i];
        fB[i] = g_feats[bj * 640 + i];
    }
    __syncthreads();

    int r = tid >> 1;
    int cbase = (tid & 1) * 64;
    float f0 = fA[r * 5 + 0], f1 = fA[r * 5 + 1], f2 = fA[r * 5 + 2];
    float f3 = fA[r * 5 + 3], f4 = fA[r * 5 + 4];

    float sum = 0.f;
    #pragma unroll 4
    for (int c = 0; c < 64; c++) {
        const float* fb = &fB[(cbase + c) * 5];
        float t0 = f0 - fb[0], t1 = f1 - fb[1], t2 = f2 - fb[2];
        float t3 = f3 - fb[3], t4 = f4 - fb[4];
        float d = t0 * t0 + t1 * t1 + t2 * t2 + t3 * t3 + t4 * t4;
        float k = __expf(-0.5f * d);
        sum += k;
        tile[r * TSTR + cbase + c] = __half_as_ushort(__float2half_rn(k));
    }
    sum += __shfl_xor_sync(0xffffffffu, sum, 1);
    if ((tid & 1) == 0) atomicAdd(&g_rowsum[bi * 128 + r], sum);
    __syncthreads();

    unsigned short* gK = (unsigned short*)g_Kh;

    for (int o = tid * 8; o < 16384; o += 2048) {
        int rr = o >> 7, cc = o & 127;
        uint4 v = *(const uint4*)&tile[rr * TSTR + cc];
        *(uint4*)&gK[(size_t)(bi * 128 + rr) * NPIX + bj * 128 + cc] = v;
    }

    if (bi != bj) {
        if (tid < 128) {
            float s = 0.f;
            #pragma unroll 4
            for (int rr = 0; rr < 128; rr++)
                s += __half2float(__ushort_as_half(tile[rr * TSTR + tid]));
            atomicAdd(&g_rowsum[bj * 128 + tid], s);
        }
    }
}

// ===========================================================================
// Q0 = softmax(-U); nbi; seed VT
// ===========================================================================
__global__ void k_q0(const float* __restrict__ U) {
    int n = blockIdx.x * blockDim.x + threadIdx.x;
    if (n >= NPIX) return;
    float nb = rsqrtf(g_rowsum[n]);
    g_nbi[n] = nb;
    float lg[LAB];
    float mx = -1e30f;
    #pragma unroll
    for (int l = 0; l < LAB; l++) {
        float v = -U[l * NPIX + n];
        lg[l] = v; mx = fmaxf(mx, v);
    }
    float se = 0.f;
    #pragma unroll
    for (int l = 0; l < LAB; l++) { lg[l] = __expf(lg[l] - mx); se += lg[l]; }
    float inv = 1.0f / se;
    #pragma unroll
    for (int l = 0; l < LAB; l++) {
        float q = lg[l] * inv;
        g_Q[l * NPIX + n] = q;
        g_VT[l * NPIX + n] = __float2half_rn(nb * q);
    }
}

// ===========================================================================
// Bilateral GEMM (fp16 HMMA), 4-way k-split + fused spatial y-pass.
// Diagonal-wavefront schedule: tile-row i processes tile-col j at step
// t=(i+j)%72, so the direct reader (row i) and transposed reader (row j) of
// stored tile (i,j) access it at the SAME step -> second access is an L2 hit.
// ===========================================================================
#define KSPLIT 4
#define NS     4
#define NCHS   36            // chunks (64-wide) per CTA = 18 tile-steps x 2
#define STAGE  11264         // 8192 (A: 64x128B) + 3072 (B: 24x128B)
#define SMEM_BIL (NS * STAGE)

__device__ __forceinline__ void bil_load_stage(uint32_t base, int s,
                                               int rowBase, int c0, int tid,
                                               bool tr) {
    uint32_t sA = base + s * STAGE;
    uint32_t sB = sA + 8192;
    #pragma unroll
    for (int it = 0; it < 6; it++) {
        int u = tid + it * 128;             // 704 16B units total
        if (u < 512) {
            int r = u >> 3, j = u & 7;
            const __half* src = tr
                ? g_Kh + (size_t)(c0 + r) * NPIX + rowBase + j * 8
                : g_Kh + (size_t)(rowBase + r) * NPIX + c0 + j * 8;
            cp16(sA + swz(r * 128 + j * 16), src);
        } else if (u < 704) {
            int v = u - 512;
            int n = v >> 3, j = v & 7;
            cp16(sB + swz(n * 128 + j * 16),
                 g_VT + (size_t)n * NPIX + c0 + j * 8);
        }
    }
    asm volatile("cp.async.commit_group;" ::: "memory");
}

// chunk index m (0..35) -> (c0, tr) under the diagonal-wavefront schedule
__device__ __forceinline__ void chunk_addr(int split, int myTile, int m,
                                           int& c0, bool& tr) {
    int t = split * (NCHS / 2) + (m >> 1);      // global tile-step 0..71
    int j = t - myTile;
    if (j < 0) j += NBLK;
    c0 = j * 128 + (m & 1) * 64;
    tr = j < myTile;
}

__global__ void __launch_bounds__(128, 4) k_bil() {
    extern __shared__ char smem[];
    uint32_t base = smem_u32(smem);
    int tid = threadIdx.x;
    int wid = tid >> 5, lane = tid & 31;
    int split = blockIdx.x & (KSPLIT - 1);
    int rowBase = (blockIdx.x >> 2) * 64;
    int myTile = rowBase >> 7;

    // lane geometry
    int ar = (lane & 7) + ((lane >> 3) & 1) * 8;
    int au = (lane >> 4) & 1;
    int tr_row8 = ((lane >> 4) & 1) * 8 + (lane & 7);
    int tr_colB = wid * 32 + ((lane >> 3) & 1) * 16;
    int bl = lane & 15;
    int brr = bl & 7;
    int bu = (bl >> 3) & 1;

    float d[3][4];
    #pragma unroll
    for (int t = 0; t < 3; t++)
        #pragma unroll
        for (int k = 0; k < 4; k++) d[t][k] = 0.f;

    #pragma unroll
    for (int jj = 0; jj < NS - 1; jj++) {
        int c0; bool tr;
        chunk_addr(split, myTile, jj, c0, tr);
        bil_load_stage(base, jj, rowBase, c0, tid, tr);
    }

    // ---- fused spatial y-pass (hides under cp.async streaming) ----
    {
        int stride = gridDim.x * blockDim.x;
        for (int t = blockIdx.x * blockDim.x + tid; t < LAB * NPIX; t += stride) {
            int l = t / NPIX, n = t - l * NPIX;
            int y = n / WW, x = n - y * WW;
            float s = 0.f;
            #pragma unroll
            for (int dd = -RAD; dd <= RAD; dd++) {
                int yy = y + dd;
                if ((unsigned)yy < HH) {
                    int m = yy * WW + x;
                    s += g_kw[dd + RAD] * g_nsp[m] * g_Q[l * NPIX + m];
                }
            }
            g_tmp[t] = s;
        }
    }

    for (int i = 0; i < NCHS; i++) {
        int rem = (NCHS - 1) - i;
        if      (rem >= 2) asm volatile("cp.async.wait_group 2;" ::: "memory");
        else if (rem == 1) asm volatile("cp.async.wait_group 1;" ::: "memory");
        else               asm volatile("cp.async.wait_group 0;" ::: "memory");
        __syncthreads();

        uint32_t sA = base + (i % NS) * STAGE;
        uint32_t sB = sA + 8192;
        int c0_cur; bool tr;
        chunk_addr(split, myTile, i, c0_cur, tr);

        #pragma unroll
        for (int kk = 0; kk < 4; kk++) {
            uint32_t a0, a1, a2, a3;
            if (!tr) {
                uint32_t aoff = (uint32_t)((wid * 16 + ar) * 128 + (kk * 2 + au) * 16);
                asm volatile("ldmatrix.sync.aligned.m8n8.x4.shared.b16 {%0,%1,%2,%3}, [%4];"
                             : "=r"(a0), "=r"(a1), "=r"(a2), "=r"(a3)
                             : "r"(sA + swz(aoff)));
            } else {
                uint32_t aoff = (uint32_t)((kk * 16 + tr_row8) * 128 + tr_colB);
                asm volatile("ldmatrix.sync.aligned.m8n8.x4.trans.shared.b16 {%0,%1,%2,%3}, [%4];"
                             : "=r"(a0), "=r"(a1), "=r"(a2), "=r"(a3)
                             : "r"(sA + swz(aoff)));
            }
            #pragma unroll
            for (int t = 0; t < 3; t++) {
                uint32_t b0, b1;
                uint32_t boff = (uint32_t)((t * 8 + brr) * 128 + (kk * 2 + bu) * 16);
                asm volatile("ldmatrix.sync.aligned.m8n8.x2.shared.b16 {%0,%1}, [%2];"
                             : "=r"(b0), "=r"(b1)
                             : "r"(sB + swz(boff)));
                asm volatile("mma.sync.aligned.m16n8k16.row.col.f32.f16.f16.f32 "
                             "{%0,%1,%2,%3}, {%4,%5,%6,%7}, {%8,%9}, {%0,%1,%2,%3};"
                             : "+f"(d[t][0]), "+f"(d[t][1]), "+f"(d[t][2]), "+f"(d[t][3])
                             : "r"(a0), "r"(a1), "r"(a2), "r"(a3), "r"(b0), "r"(b1));
            }
        }
        __syncthreads();

        int n = i + NS - 1;
        if (n < NCHS) {
            int nc0; bool ntr;
            chunk_addr(split, myTile, n, nc0, ntr);
            bil_load_stage(base, n % NS, rowBase, nc0, tid, ntr);
        }
    }

    float* Cp = g_Cp + (size_t)split * NPIX * LAB;
    int row = rowBase + wid * 16 + (lane >> 2);
    #pragma unroll
    for (int t = 0; t < 3; t++) {
        int col = t * 8 + (lane & 3) * 2;
        if (col < LAB)     Cp[row * LAB + col]           = d[t][0];
        if (col + 1 < LAB) Cp[row * LAB + col + 1]       = d[t][1];
        if (col < LAB)     Cp[(row + 8) * LAB + col]     = d[t][2];
        if (col + 1 < LAB) Cp[(row + 8) * LAB + col + 1] = d[t][3];
    }
}

// ===========================================================================
// Combine: one CTA per image row; 384 threads = 96 pixels x 4 label groups
// ===========================================================================
__global__ void __launch_bounds__(384) k_combine(const float* __restrict__ U,
                                                 float* __restrict__ out,
                                                 int writeOut) {
    __shared__ float tmpS[LAB * 114];     // padded row: idx l*114 + (x+d)
    __shared__ float red[4 * 96];

    int y = blockIdx.x;
    int tid = threadIdx.x;
    int x = tid % 96;
    int g = tid / 96;                     // label group 0..3

    for (int i = tid; i < LAB * 114; i += 384) {
        int l = i / 114, xx = i - l * 114;
        float v = 0.f;
        if (xx >= 9 && xx < 105) v = g_tmp[l * NPIX + y * WW + (xx - 9)];
        tmpS[i] = v;
    }
    __syncthreads();

    int n = y * WW + x;
    float nsp = g_nsp[n];
    float nbi = g_nbi[n];
    int lbase = g * 6;
    int lcnt = (g == 3) ? 3 : 6;

    float v[6], e[6];
    float mx = -1e30f;
    #pragma unroll
    for (int j = 0; j < 6; j++) {
        if (j < lcnt) {
            int l = lbase + j;
            float s = 0.f;
            #pragma unroll
            for (int dd = 0; dd < KWD; dd++)
                s += g_kw[dd] * tmpS[l * 114 + x + dd];
            float c = g_Cp[n * LAB + l]
                    + g_Cp[1 * NPIX * LAB + n * LAB + l]
                    + g_Cp[2 * NPIX * LAB + n * LAB + l]
                    + g_Cp[3 * NPIX * LAB + n * LAB + l];
            float vv = -U[l * NPIX + n] + 3.0f * nsp * s + 10.0f * nbi * c;
            v[j] = vv;
            mx = fmaxf(mx, vv);
        }
    }
    red[g * 96 + x] = mx;
    __syncthreads();
    mx = fmaxf(fmaxf(red[x], red[96 + x]), fmaxf(red[192 + x], red[288 + x]));

    float se = 0.f;
    #pragma unroll
    for (int j = 0; j < 6; j++) {
        if (j < lcnt) { e[j] = __expf(v[j] - mx); se += e[j]; }
    }
    __syncthreads();
    red[g * 96 + x] = se;
    __syncthreads();
    se = red[x] + red[96 + x] + red[192 + x] + red[288 + x];
    float inv = 1.0f / se;

    #pragma unroll
    for (int j = 0; j < 6; j++) {
        if (j < lcnt) {
            int l = lbase + j;
            float q = e[j] * inv;
            g_Q[l * NPIX + n] = q;
            g_VT[l * NPIX + n] = __float2half_rn(nbi * q);
            if (writeOut) out[l * NPIX + n] = q;
        }
    }
}

// ===========================================================================
extern "C" void kernel_launch(void* const* d_in, const int* in_sizes, int n_in,
                              void* d_out, int out_size) {
    const float* U = (const float*)d_in[0];   // [1,21,96,96]
    const float* I = (const float*)d_in[1];   // [1,3,96,96]
    float* out = (float*)d_out;               // [1,21,96,96]

    cudaFuncSetAttribute(k_bil, cudaFuncAttributeMaxDynamicSharedMemorySize, SMEM_BIL);

    k_prep<<<36, 256>>>(I);
    k_buildK<<<NBLK * (NBLK + 1) / 2, 256>>>();
    k_q0<<<72, 128>>>(U);

    for (int it = 0; it < 10; it++) {
        k_bil<<<(NPIX / 64) * KSPLIT, 128, SMEM_BIL>>>();
        k_combine<<<HH, 384>>>(U, out, it == 9 ? 1 : 0);
    }
}

// round 11
// speedup vs baseline: 1.1310x; 1.1310x over previous
#include <cuda_runtime.h>
#include <cuda_fp16.h>
#include <cstdint>

#define NPIX 9216
#define LAB  21
#define HH   96
#define WW   96
#define RAD  9
#define KWD  (2*RAD+1)
#define NBLK 72                 // 128-tiles per side
#define NB64 144                // 64-blocks per side

// ---- scratch (device globals: allocation-free kernel_launch) ----
// K as pre-swizzled 8KB blobs: blob(I,J) = K rows I*64..+63, cols J*64..+63,
// stored 64 rows x 128B with xor-swizzle baked in. Only blobs with
// (I>>1) <= (J>>1) (upper-tri 128-tiles) are written/used.
__device__ __align__(128) unsigned char g_Kb[(size_t)NB64 * NB64 * 8192];
// VT blobs: per 64-col chunk, 24 rows (labels, 21..23 zero) x 128B swizzled.
__device__ __align__(128) unsigned char g_Vb[NB64 * 3072];
__device__ float g_feats[NPIX * 5];
__device__ float g_rowsum[NPIX];
__device__ float g_nbi[NPIX];
__device__ float g_nsp[NPIX];
__device__ float g_kw[KWD];
__device__ float g_Q[LAB * NPIX];              // [L][N]
__device__ float g_tmp[LAB * NPIX];            // y-conv intermediate
__device__ float g_Cp[4 * NPIX * LAB];         // k-split partials, [s][N][L]

// ===========================================================================
// helpers
// ===========================================================================
__device__ __forceinline__ uint32_t smem_u32(const void* p) {
    uint32_t a;
    asm("{ .reg .u64 t; cvta.to.shared.u64 t, %1; cvt.u32.u64 %0, t; }" : "=r"(a) : "l"(p));
    return a;
}
__device__ __forceinline__ uint32_t swz(uint32_t off) {   // 8x128B xor swizzle
    return off ^ ((off >> 3) & 0x70);
}
__device__ __forceinline__ void mbar_init(uint32_t a, uint32_t cnt) {
    asm volatile("mbarrier.init.shared.b64 [%0], %1;" :: "r"(a), "r"(cnt) : "memory");
}
__device__ __forceinline__ void mbar_expect(uint32_t a, uint32_t tx) {
    asm volatile("mbarrier.arrive.expect_tx.shared.b64 _, [%0], %1;"
                 :: "r"(a), "r"(tx) : "memory");
}
__device__ __forceinline__ void mbar_wait(uint32_t a, uint32_t parity) {
    uint32_t done;
    asm volatile("{\n\t.reg .pred p;\n\t"
                 "mbarrier.try_wait.parity.shared.b64 p, [%1], %2;\n\t"
                 "selp.b32 %0, 1, 0, p;\n\t}"
                 : "=r"(done) : "r"(a), "r"(parity) : "memory");
    if (!done) {
        asm volatile("{\n\t.reg .pred P1;\n\t"
                     "WL_%=:\n\t"
                     "mbarrier.try_wait.parity.shared.b64 P1, [%0], %1;\n\t"
                     "@P1 bra.uni WD_%=;\n\t"
                     "bra.uni WL_%=;\n\t"
                     "WD_%=:\n\t}"
                     :: "r"(a), "r"(parity) : "memory");
    }
}
__device__ __forceinline__ void bulk_g2s(uint32_t dst, const void* src,
                                         uint32_t bytes, uint32_t mbar) {
    asm volatile("cp.async.bulk.shared::cluster.global.mbarrier::complete_tx::bytes "
                 "[%0], [%1], %2, [%3];"
                 :: "r"(dst), "l"(src), "r"(bytes), "r"(mbar) : "memory");
}
// VT blob store of one half at (label l, pixel n)
__device__ __forceinline__ void vt_store(int l, int n, __half v) {
    uint32_t off = (uint32_t)(l * 128 + ((n & 63) >> 3) * 16);
    off = swz(off);
    *(__half*)(g_Vb + (size_t)(n >> 6) * 3072 + off + (uint32_t)(n & 7) * 2) = v;
}

// ===========================================================================
// Prep
// ===========================================================================
__global__ void k_prep(const float* __restrict__ I) {
    int n = blockIdx.x * blockDim.x + threadIdx.x;
    if (n >= NPIX) return;
    int y = n / WW, x = n % WW;

    if (n < KWD) {
        float d = (float)(n - RAD) / 3.0f;
        g_kw[n] = expf(-0.5f * d * d);
    }
    float sy = 0.f, sx = 0.f;
    #pragma unroll
    for (int d = -RAD; d <= RAD; d++) {
        float t = (float)d / 3.0f;
        float w = expf(-0.5f * t * t);
        if ((unsigned)(y + d) < HH) sy += w;
        if ((unsigned)(x + d) < WW) sx += w;
    }
    g_nsp[n] = rsqrtf(sy * sx);
    g_rowsum[n] = 0.f;

    g_feats[n * 5 + 0] = (float)x / 80.0f;
    g_feats[n * 5 + 1] = (float)y / 80.0f;
    g_feats[n * 5 + 2] = I[0 * NPIX + n] / 13.0f;
    g_feats[n * 5 + 3] = I[1 * NPIX + n] / 13.0f;
    g_feats[n * 5 + 4] = I[2 * NPIX + n] / 13.0f;

    // zero pad rows 21..23 of each VT blob: 144 blobs x 3 rows x 8 units
    if (n < NB64 * 3 * 8) {
        int blob = n / 24, rem = n % 24;
        int l = LAB + rem / 8, u = rem % 8;
        uint32_t off = swz((uint32_t)(l * 128 + u * 16));
        uint4 z = {0u, 0u, 0u, 0u};
        *(uint4*)(g_Vb + (size_t)blob * 3072 + off) = z;
    }
}

// ===========================================================================
// Build K (fp16), upper-triangle 128x128 tiles -> 4 pre-swizzled 8KB blobs.
// Row sums via atomics (direct rows fp32; mirror rows via column sums).
// ===========================================================================
#define TSTR 136
__global__ void __launch_bounds__(256) k_buildK() {
    __shared__ float fA[128 * 5];
    __shared__ float fB[128 * 5];
    __shared__ __align__(16) unsigned short tile[128 * TSTR];

    int id = blockIdx.x;
    int bi;
    {
        float b = 2.f * NBLK + 1.f;
        bi = (int)((b - sqrtf(b * b - 8.f * (float)id)) * 0.5f);
        if (bi < 0) bi = 0;
        if (bi > NBLK - 1) bi = NBLK - 1;
        while (bi * NBLK - bi * (bi - 1) / 2 > id) bi--;
        while ((bi + 1) * NBLK - (bi + 1) * bi / 2 <= id) bi++;
    }
    int bj = bi + (id - (bi * NBLK - bi * (bi - 1) / 2));

    int tid = threadIdx.x;
    for (int i = tid; i < 640; i += 256) {
        fA[i] = g_feats[bi * 640 + i];
        fB[i] = g_feats[bj * 640 + i];
    }
    __syncthreads();

    int r = tid >> 1;
    int cbase = (tid & 1) * 64;
    float f0 = fA[r * 5 + 0], f1 = fA[r * 5 + 1], f2 = fA[r * 5 + 2];
    float f3 = fA[r * 5 + 3], f4 = fA[r * 5 + 4];

    float sum = 0.f;
    #pragma unroll 4
    for (int c = 0; c < 64; c++) {
        const float* fb = &fB[(cbase + c) * 5];
        float t0 = f0 - fb[0], t1 = f1 - fb[1], t2 = f2 - fb[2];
        float t3 = f3 - fb[3], t4 = f4 - fb[4];
        float d = t0 * t0 + t1 * t1 + t2 * t2 + t3 * t3 + t4 * t4;
        float k = __expf(-0.5f * d);
        sum += k;
        tile[r * TSTR + cbase + c] = __half_as_ushort(__float2half_rn(k));
    }
    sum += __shfl_xor_sync(0xffffffffu, sum, 1);
    if ((tid & 1) == 0) atomicAdd(&g_rowsum[bi * 128 + r], sum);
    __syncthreads();

    // write 4 pre-swizzled blobs: (2bi+u, 2bj+v)
    #pragma unroll
    for (int k = 0; k < 8; k++) {
        int w = tid + k * 256;          // 0..2047 units of 16B
        int b = w >> 9;                  // blob 0..3
        int u = b >> 1, v = b & 1;
        int unit = w & 511;
        int rr = unit >> 3, j = unit & 7;
        uint32_t off = swz((uint32_t)(rr * 128 + j * 16));
        uint4 val = *(const uint4*)&tile[(u * 64 + rr) * TSTR + v * 64 + j * 8];
        *(uint4*)(g_Kb + ((size_t)((2 * bi + u) * NB64 + (2 * bj + v))) * 8192 + off) = val;
    }

    if (bi != bj) {
        if (tid < 128) {
            float s = 0.f;
            #pragma unroll 4
            for (int rr = 0; rr < 128; rr++)
                s += __half2float(__ushort_as_half(tile[rr * TSTR + tid]));
            atomicAdd(&g_rowsum[bj * 128 + tid], s);
        }
    }
}

// ===========================================================================
// Q0 = softmax(-U); nbi; seed VT blobs
// ===========================================================================
__global__ void k_q0(const float* __restrict__ U) {
    int n = blockIdx.x * blockDim.x + threadIdx.x;
    if (n >= NPIX) return;
    float nb = rsqrtf(g_rowsum[n]);
    g_nbi[n] = nb;
    float lg[LAB];
    float mx = -1e30f;
    #pragma unroll
    for (int l = 0; l < LAB; l++) {
        float v = -U[l * NPIX + n];
        lg[l] = v; mx = fmaxf(mx, v);
    }
    float se = 0.f;
    #pragma unroll
    for (int l = 0; l < LAB; l++) { lg[l] = __expf(lg[l] - mx); se += lg[l]; }
    float inv = 1.0f / se;
    #pragma unroll
    for (int l = 0; l < LAB; l++) {
        float q = lg[l] * inv;
        g_Q[l * NPIX + n] = q;
        vt_store(l, n, __float2half_rn(nb * q));
    }
}

// ===========================================================================
// Bilateral GEMM (fp16 HMMA), 4-way k-split + fused spatial y-pass.
// Stage fill = 2 cp.async.bulk copies issued by thread 0 (A blob 8KB + V blob
// 3KB, both pre-swizzled in GMEM), completion via mbarrier expect_tx.
// ===========================================================================
#define KSPLIT 4
#define NS     4
#define NCHS   36            // 144 / KSPLIT
#define STAGE  11264         // 8192 (A) + 3072 (B)
#define SMEM_BIL (NS * STAGE)

__global__ void __launch_bounds__(128, 4) k_bil() {
    extern __shared__ char smem[];
    __shared__ __align__(8) unsigned long long mbars[NS];
    uint32_t base = smem_u32(smem);
    uint32_t mb0 = smem_u32(mbars);
    int tid = threadIdx.x;
    int wid = tid >> 5, lane = tid & 31;
    int split = blockIdx.x & (KSPLIT - 1);
    int rowBase = (blockIdx.x >> 2) * 64;
    int myTile = rowBase >> 7;
    int rBlk = rowBase >> 6;
    int c0base = split * NCHS * 64;

    // lane geometry
    int ar = (lane & 7) + ((lane >> 3) & 1) * 8;
    int au = (lane >> 4) & 1;
    int tr_row8 = ((lane >> 4) & 1) * 8 + (lane & 7);
    int tr_colB = wid * 32 + ((lane >> 3) & 1) * 16;
    int bl = lane & 15;
    int brr = bl & 7;
    int bu = (bl >> 3) & 1;

    float d[3][4];
    #pragma unroll
    for (int t = 0; t < 3; t++)
        #pragma unroll
        for (int k = 0; k < 4; k++) d[t][k] = 0.f;

    if (tid == 0) {
        #pragma unroll
        for (int s = 0; s < NS; s++) mbar_init(mb0 + 8 * s, 1);
    }
    __syncthreads();

    // prologue: issue chunks 0..NS-2
    if (tid == 0) {
        #pragma unroll
        for (int j = 0; j < NS - 1; j++) {
            int c0 = c0base + j * 64;
            int cBlk = c0 >> 6;
            bool tr = (c0 >> 7) < myTile;
            const unsigned char* srcA = tr
                ? g_Kb + ((size_t)(cBlk * NB64 + rBlk)) * 8192
                : g_Kb + ((size_t)(rBlk * NB64 + cBlk)) * 8192;
            uint32_t mb = mb0 + 8 * j;
            mbar_expect(mb, STAGE);
            bulk_g2s(base + j * STAGE, srcA, 8192, mb);
            bulk_g2s(base + j * STAGE + 8192, g_Vb + (size_t)cBlk * 3072, 3072, mb);
        }
    }

    // ---- fused spatial y-pass (overlaps with bulk streaming) ----
    {
        int stride = gridDim.x * blockDim.x;
        for (int t = blockIdx.x * blockDim.x + tid; t < LAB * NPIX; t += stride) {
            int l = t / NPIX, n = t - l * NPIX;
            int y = n / WW, x = n - y * WW;
            float s = 0.f;
            #pragma unroll
            for (int dd = -RAD; dd <= RAD; dd++) {
                int yy = y + dd;
                if ((unsigned)yy < HH) {
                    int m = yy * WW + x;
                    s += g_kw[dd + RAD] * g_nsp[m] * g_Q[l * NPIX + m];
                }
            }
            g_tmp[t] = s;
        }
    }

    for (int i = 0; i < NCHS; i++) {
        int s = i & (NS - 1);
        mbar_wait(mb0 + 8 * s, (uint32_t)((i >> 2) & 1));

        uint32_t sA = base + s * STAGE;
        uint32_t sB = sA + 8192;
        int c0 = c0base + i * 64;
        bool tr = (c0 >> 7) < myTile;

        #pragma unroll
        for (int kk = 0; kk < 4; kk++) {
            uint32_t a0, a1, a2, a3;
            if (!tr) {
                uint32_t aoff = (uint32_t)((wid * 16 + ar) * 128 + (kk * 2 + au) * 16);
                asm volatile("ldmatrix.sync.aligned.m8n8.x4.shared.b16 {%0,%1,%2,%3}, [%4];"
                             : "=r"(a0), "=r"(a1), "=r"(a2), "=r"(a3)
                             : "r"(sA + swz(aoff)));
            } else {
                uint32_t aoff = (uint32_t)((kk * 16 + tr_row8) * 128 + tr_colB);
                asm volatile("ldmatrix.sync.aligned.m8n8.x4.trans.shared.b16 {%0,%1,%2,%3}, [%4];"
                             : "=r"(a0), "=r"(a1), "=r"(a2), "=r"(a3)
                             : "r"(sA + swz(aoff)));
            }
            #pragma unroll
            for (int t = 0; t < 3; t++) {
                uint32_t b0, b1;
                uint32_t boff = (uint32_t)((t * 8 + brr) * 128 + (kk * 2 + bu) * 16);
                asm volatile("ldmatrix.sync.aligned.m8n8.x2.shared.b16 {%0,%1}, [%2];"
                             : "=r"(b0), "=r"(b1)
                             : "r"(sB + swz(boff)));
                asm volatile("mma.sync.aligned.m16n8k16.row.col.f32.f16.f16.f32 "
                             "{%0,%1,%2,%3}, {%4,%5,%6,%7}, {%8,%9}, {%0,%1,%2,%3};"
                             : "+f"(d[t][0]), "+f"(d[t][1]), "+f"(d[t][2]), "+f"(d[t][3])
                             : "r"(a0), "r"(a1), "r"(a2), "r"(a3), "r"(b0), "r"(b1));
            }
        }
        __syncthreads();   // all warps done reading stage (i-1)%NS (and s)

        int n = i + NS - 1;
        if (n < NCHS && tid == 0) {
            int sn = n & (NS - 1);
            int nc0 = c0base + n * 64;
            int cBlk = nc0 >> 6;
            bool ntr = (nc0 >> 7) < myTile;
            const unsigned char* srcA = ntr
                ? g_Kb + ((size_t)(cBlk * NB64 + rBlk)) * 8192
                : g_Kb + ((size_t)(rBlk * NB64 + cBlk)) * 8192;
            uint32_t mb = mb0 + 8 * sn;
            mbar_expect(mb, STAGE);
            bulk_g2s(base + sn * STAGE, srcA, 8192, mb);
            bulk_g2s(base + sn * STAGE + 8192, g_Vb + (size_t)cBlk * 3072, 3072, mb);
        }
    }

    float* Cp = g_Cp + (size_t)split * NPIX * LAB;
    int row = rowBase + wid * 16 + (lane >> 2);
    #pragma unroll
    for (int t = 0; t < 3; t++) {
        int col = t * 8 + (lane & 3) * 2;
        if (col < LAB)     Cp[row * LAB + col]           = d[t][0];
        if (col + 1 < LAB) Cp[row * LAB + col + 1]       = d[t][1];
        if (col < LAB)     Cp[(row + 8) * LAB + col]     = d[t][2];
        if (col + 1 < LAB) Cp[(row + 8) * LAB + col + 1] = d[t][3];
    }
}

// ===========================================================================
// Combine: one CTA per image row; 384 threads = 96 pixels x 4 label groups
// ===========================================================================
__global__ void __launch_bounds__(384) k_combine(const float* __restrict__ U,
                                                 float* __restrict__ out,
                                                 int writeOut) {
    __shared__ float tmpS[LAB * 114];
    __shared__ float red[4 * 96];

    int y = blockIdx.x;
    int tid = threadIdx.x;
    int x = tid % 96;
    int g = tid / 96;

    for (int i = tid; i < LAB * 114; i += 384) {
        int l = i / 114, xx = i - l * 114;
        float v = 0.f;
        if (xx >= 9 && xx < 105) v = g_tmp[l * NPIX + y * WW + (xx - 9)];
        tmpS[i] = v;
    }
    __syncthreads();

    int n = y * WW + x;
    float nsp = g_nsp[n];
    float nbi = g_nbi[n];
    int lbase = g * 6;
    int lcnt = (g == 3) ? 3 : 6;

    float v[6], e[6];
    float mx = -1e30f;
    #pragma unroll
    for (int j = 0; j < 6; j++) {
        if (j < lcnt) {
            int l = lbase + j;
            float s = 0.f;
            #pragma unroll
            for (int dd = 0; dd < KWD; dd++)
                s += g_kw[dd] * tmpS[l * 114 + x + dd];
            float c = g_Cp[n * LAB + l]
                    + g_Cp[1 * NPIX * LAB + n * LAB + l]
                    + g_Cp[2 * NPIX * LAB + n * LAB + l]
                    + g_Cp[3 * NPIX * LAB + n * LAB + l];
            float vv = -U[l * NPIX + n] + 3.0f * nsp * s + 10.0f * nbi * c;
            v[j] = vv;
            mx = fmaxf(mx, vv);
        }
    }
    red[g * 96 + x] = mx;
    __syncthreads();
    mx = fmaxf(fmaxf(red[x], red[96 + x]), fmaxf(red[192 + x], red[288 + x]));

    float se = 0.f;
    #pragma unroll
    for (int j = 0; j < 6; j++) {
        if (j < lcnt) { e[j] = __expf(v[j] - mx); se += e[j]; }
    }
    __syncthreads();
    red[g * 96 + x] = se;
    __syncthreads();
    se = red[x] + red[96 + x] + red[192 + x] + red[288 + x];
    float inv = 1.0f / se;

    #pragma unroll
    for (int j = 0; j < 6; j++) {
        if (j < lcnt) {
            int l = lbase + j;
            float q = e[j] * inv;
            g_Q[l * NPIX + n] = q;
            vt_store(l, n, __float2half_rn(nbi * q));
            if (writeOut) out[l * NPIX + n] = q;
        }
    }
}

// ===========================================================================
extern "C" void kernel_launch(void* const* d_in, const int* in_sizes, int n_in,
                              void* d_out, int out_size) {
    const float* U = (const float*)d_in[0];   // [1,21,96,96]
    const float* I = (const float*)d_in[1];   // [1,3,96,96]
    float* out = (float*)d_out;               // [1,21,96,96]

    cudaFuncSetAttribute(k_bil, cudaFuncAttributeMaxDynamicSharedMemorySize, SMEM_BIL);

    k_prep<<<36, 256>>>(I);
    k_buildK<<<NBLK * (NBLK + 1) / 2, 256>>>();
    k_q0<<<72, 128>>>(U);

    for (int it = 0; it < 10; it++) {
        k_bil<<<(NPIX / 64) * KSPLIT, 128, SMEM_BIL>>>();
        k_combine<<<HH, 384>>>(U, out, it == 9 ? 1 : 0);
    }
}